// round 1
// baseline (speedup 1.0000x reference)
#include <cuda_runtime.h>

// LoKr: y = x @ kron(w1^T, w2^T) * (alpha/r)
//   x: (8192, 4096) fp32; w1_a (16,64), w1_b (64,16), w2_a (16,64), w2_b (64,16)
// Per row (viewed as X[64][64], idx m*64+n):
//   Y[l,k] = S * sum_{m,n,j,t} X[m,n] w1a[j,l] w1b[m,j] w2a[t,k] w2b[n,t]
// Factored:
//   P[j,n] = sum_m w1b[m,j] X[m,n]          (16x64)
//   C[j,t] = sum_n P[j,n] w2b[n,t]          (16x16)
//   Q[l,t] = S * sum_j w1a[j,l] C[j,t]      (64x16)
//   Y[l,k] = sum_t Q[l,t] w2a[t,k]          (64x64)

using u64 = unsigned long long;

static constexpr float SCALING = 1.0f / 16.0f;   // alpha/r = 1/16

// Packed f32x2 FMA (Blackwell): d = a*b + c on two lanes at once.
__device__ __forceinline__ float2 ffma2(float2 a, float2 b, float2 c) {
    float2 d;
    asm("{\n\t"
        ".reg .b64 ra, rb, rc, rd;\n\t"
        "mov.b64 ra, {%2,%3};\n\t"
        "mov.b64 rb, {%4,%5};\n\t"
        "mov.b64 rc, {%6,%7};\n\t"
        "fma.rn.f32x2 rd, ra, rb, rc;\n\t"
        "mov.b64 {%0,%1}, rd;\n\t"
        "}"
        : "=f"(d.x), "=f"(d.y)
        : "f"(a.x), "f"(a.y), "f"(b.x), "f"(b.y), "f"(c.x), "f"(c.y));
    return d;
}

// Precomputed packed weight layouts (device scratch; no allocation).
__device__ float4 g_w1bp[256];   // [m*4 + jg] = {w1b[m,jg], w1b[m,jg+4], w1b[m,jg+8], w1b[m,jg+12]}
__device__ float2 g_w2bp[512];   // [np*16 + t] = {w2b[2np,t], w2b[2np+1,t]}
__device__ float2 g_w1ap[512];   // [jp*64 + l] = S * {w1a[2jp,l], w1a[2jp+1,l]}

__global__ void lokr_prep(const float* __restrict__ w1a,
                          const float* __restrict__ w1b,
                          const float* __restrict__ w2b)
{
    int tid = threadIdx.x;
    if (tid < 256) {
        int m = tid >> 2, jg = tid & 3;
        g_w1bp[tid] = make_float4(w1b[m * 16 + jg],
                                  w1b[m * 16 + jg + 4],
                                  w1b[m * 16 + jg + 8],
                                  w1b[m * 16 + jg + 12]);
    }
    for (int idx = tid; idx < 512; idx += 256) {
        int np = idx >> 4, t = idx & 15;
        g_w2bp[idx] = make_float2(w2b[(2 * np) * 16 + t], w2b[(2 * np + 1) * 16 + t]);
        int jp = idx >> 6, l = idx & 63;
        g_w1ap[idx] = make_float2(SCALING * w1a[(2 * jp) * 64 + l],
                                  SCALING * w1a[(2 * jp + 1) * 64 + l]);
    }
}

__global__ void __launch_bounds__(256) lokr_main(
    const float* __restrict__ x,
    const float* __restrict__ w2a,
    float* __restrict__ out,
    int rows)
{
    __shared__ __align__(16) float  Xs[4096];      // 16 KB: one row as X[64][64]
    __shared__ __align__(16) float  Ps[1024];      // P[j*64+n]
    __shared__ __align__(16) float  Qs[1024];      // Q[l*16+t]
    __shared__ __align__(16) float  Cs[256];       // C stored as Cs[t*16+j] (j-adjacent pairs)
    __shared__ __align__(16) float4 w1bp_s[256];
    __shared__ __align__(16) float2 w2bp_s[512];
    __shared__ __align__(16) float2 w1ap_s[512];
    __shared__ __align__(16) float  w2a_s[1024];   // row-major (16,64)

    const int tid = threadIdx.x;

    // Load all weights into smem once.
    w1bp_s[tid]        = g_w1bp[tid];
    w2bp_s[tid]        = g_w2bp[tid];
    w2bp_s[tid + 256]  = g_w2bp[tid + 256];
    w1ap_s[tid]        = g_w1ap[tid];
    w1ap_s[tid + 256]  = g_w1ap[tid + 256];
    reinterpret_cast<float4*>(w2a_s)[tid] = reinterpret_cast<const float4*>(w2a)[tid];

    int row = blockIdx.x;
    if (row >= rows) return;          // uniform per block

    const int stride = gridDim.x;

    // Preload first row into registers.
    float4 stage[4];
    {
        const float4* src = reinterpret_cast<const float4*>(x) + (size_t)row * 1024;
#pragma unroll
        for (int i = 0; i < 4; i++) stage[i] = src[tid + 256 * i];
    }

    for (; row < rows; row += stride) {
        // Commit staged row to smem (all prior readers of Xs are past the last barrier chain).
        {
            float4* Xv = reinterpret_cast<float4*>(Xs);
#pragma unroll
            for (int i = 0; i < 4; i++) Xv[tid + 256 * i] = stage[i];
        }
        __syncthreads();

        // Prefetch next row; its consumption is ~1300 cycles away -> LDG latency hidden.
        {
            int nrow = row + stride;
            if (nrow < rows) {
                const float4* src = reinterpret_cast<const float4*>(x) + (size_t)nrow * 1024;
#pragma unroll
                for (int i = 0; i < 4; i++) stage[i] = src[tid + 256 * i];
            }
        }

        // ---- Step 1: P[j,n] = sum_m w1b[m,j] * X[m,n] ----
        // thread (jg = tid>>6 in 0..3, n = tid&63): owns j in {jg, jg+4, jg+8, jg+12}
        {
            const int n = tid & 63, jg = tid >> 6;
            float2 a0 = make_float2(0.f, 0.f), a1 = make_float2(0.f, 0.f);
#pragma unroll 16
            for (int m = 0; m < 64; m++) {
                float  xv = Xs[m * 64 + n];             // coalesced, conflict-free
                float2 xx = make_float2(xv, xv);
                float4 w  = w1bp_s[m * 4 + jg];         // warp-broadcast
                a0 = ffma2(xx, make_float2(w.x, w.y), a0);
                a1 = ffma2(xx, make_float2(w.z, w.w), a1);
            }
            Ps[(jg     ) * 64 + n] = a0.x;
            Ps[(jg +  4) * 64 + n] = a0.y;
            Ps[(jg +  8) * 64 + n] = a1.x;
            Ps[(jg + 12) * 64 + n] = a1.y;
        }
        __syncthreads();

        // ---- Step 2: C[j,t] = sum_n P[j,n] * w2b[n,t]; store Cs[t*16+j] ----
        {
            const int j = tid >> 4, t = tid & 15;
            const float2* Pp = reinterpret_cast<const float2*>(Ps + j * 64);
            float2 acc = make_float2(0.f, 0.f);
#pragma unroll
            for (int np = 0; np < 32; np++)
                acc = ffma2(Pp[np], w2bp_s[np * 16 + t], acc);
            Cs[t * 16 + j] = acc.x + acc.y;
        }
        __syncthreads();

        // ---- Step 3: Q[l,t] = S * sum_j w1a[j,l] * C[j,t]; store Qs[l*16+t] ----
        {
            const int l = tid >> 2, tq = tid & 3;
            float2 wa[8];
#pragma unroll
            for (int jp = 0; jp < 8; jp++) wa[jp] = w1ap_s[jp * 64 + l];
#pragma unroll
            for (int s = 0; s < 4; s++) {
                int t = tq + 4 * s;
                const float2* Cp = reinterpret_cast<const float2*>(Cs + t * 16);
                float2 acc = make_float2(0.f, 0.f);
#pragma unroll
                for (int jp = 0; jp < 8; jp++)
                    acc = ffma2(wa[jp], Cp[jp], acc);
                Qs[l * 16 + t] = acc.x + acc.y;
            }
        }
        __syncthreads();

        // ---- Step 4: Y[l,k] = sum_t Q[l,t] * w2a[t,k]; float4 stores ----
        // thread (kq = tid&15 -> k0 = 4*kq, lg = tid>>4): l in {lg, lg+16, lg+32, lg+48}
        {
            const int kq = tid & 15, lg = tid >> 4;
            const int k0 = kq * 4;
            float* orow = out + (size_t)row * 4096;
#pragma unroll
            for (int i = 0; i < 4; i++) {
                int l = lg + 16 * i;
                const float4* qv4 = reinterpret_cast<const float4*>(Qs + l * 16);
                float2 a01 = make_float2(0.f, 0.f), a23 = make_float2(0.f, 0.f);
#pragma unroll
                for (int u = 0; u < 4; u++) {
                    float4 qq = qv4[u];
                    {
                        float4 w = *reinterpret_cast<const float4*>(&w2a_s[(4 * u + 0) * 64 + k0]);
                        float2 qd = make_float2(qq.x, qq.x);
                        a01 = ffma2(qd, make_float2(w.x, w.y), a01);
                        a23 = ffma2(qd, make_float2(w.z, w.w), a23);
                    }
                    {
                        float4 w = *reinterpret_cast<const float4*>(&w2a_s[(4 * u + 1) * 64 + k0]);
                        float2 qd = make_float2(qq.y, qq.y);
                        a01 = ffma2(qd, make_float2(w.x, w.y), a01);
                        a23 = ffma2(qd, make_float2(w.z, w.w), a23);
                    }
                    {
                        float4 w = *reinterpret_cast<const float4*>(&w2a_s[(4 * u + 2) * 64 + k0]);
                        float2 qd = make_float2(qq.z, qq.z);
                        a01 = ffma2(qd, make_float2(w.x, w.y), a01);
                        a23 = ffma2(qd, make_float2(w.z, w.w), a23);
                    }
                    {
                        float4 w = *reinterpret_cast<const float4*>(&w2a_s[(4 * u + 3) * 64 + k0]);
                        float2 qd = make_float2(qq.w, qq.w);
                        a01 = ffma2(qd, make_float2(w.x, w.y), a01);
                        a23 = ffma2(qd, make_float2(w.z, w.w), a23);
                    }
                }
                *reinterpret_cast<float4*>(&orow[l * 64 + k0]) =
                    make_float4(a01.x, a01.y, a23.x, a23.y);
            }
        }
        __syncthreads();   // all of Qs consumed before next iteration's step 3 rewrite
    }
}

extern "C" void kernel_launch(void* const* d_in, const int* in_sizes, int n_in,
                              void* d_out, int out_size) {
    const float* x   = (const float*)d_in[0];
    const float* w1a = (const float*)d_in[1];
    const float* w1b = (const float*)d_in[2];
    const float* w2a = (const float*)d_in[3];
    const float* w2b = (const float*)d_in[4];
    float* out = (float*)d_out;

    int rows = in_sizes[0] / 4096;

    lokr_prep<<<1, 256>>>(w1a, w1b, w2b);
    lokr_main<<<296, 256>>>(x, w2a, out, rows);
}

// round 3
// speedup vs baseline: 1.5022x; 1.5022x over previous
#include <cuda_runtime.h>

// LoKr: y = x @ kron(w1^T, w2^T) * (alpha/r),  x: (8192, 4096) fp32
// Per row (X = row reshaped 64x64, idx m*64+n):
//   P[j,n] = sum_m w1b[m,j] X[m,n]          (16x64)
//   C[j,t] = sum_n P[j,n] w2b[n,t]          (16x16)
//   Q[l,t] = S * sum_j w1a[j,l] C[j,t]      (64x16)
//   Y[l,k] = sum_t Q[l,t] w2a[t,k]          (64x64)
// 4 rows per CTA iteration, 64 threads per row.

static constexpr float SCALING = 1.0f / 16.0f;   // alpha/r

// Packed f32x2 FMA (Blackwell): two fp32 FMAs per issue.
__device__ __forceinline__ float2 ffma2(float2 a, float2 b, float2 c) {
    float2 d;
    asm("{\n\t"
        ".reg .b64 ra, rb, rc, rd;\n\t"
        "mov.b64 ra, {%2,%3};\n\t"
        "mov.b64 rb, {%4,%5};\n\t"
        "mov.b64 rc, {%6,%7};\n\t"
        "fma.rn.f32x2 rd, ra, rb, rc;\n\t"
        "mov.b64 {%0,%1}, rd;\n\t"
        "}"
        : "=f"(d.x), "=f"(d.y)
        : "f"(a.x), "f"(a.y), "f"(b.x), "f"(b.y), "f"(c.x), "f"(c.y));
    return d;
}

// Dynamic smem layout (bytes):
//   [0, 65536)        Xbuf: 4 rows x 4096 floats.  Reused: P at float offset 0
//                     (4 x 1024, [r*1024 + j*64 + n]); Q at float offset 4096
//                     (4 x 1280, [r*1280 + l*20 + t], stride 20 kills bank conflicts)
//   [65536, 69632)    Cs: 4 x 256 floats  [r*256 + j*16 + t]
//   [69632, 73728)    w1bp: 256 float4  [m*4+jg] = {w1b[m][jg], [jg+4], [jg+8], [jg+12]}
//   [73728, 77824)    w2b4: 256 float4  [n*4+tg] = w2b[n][4tg..4tg+3]
//   [77824, 81920)    w1a_s: 1024 floats, S * w1a row-major [j*64+l]
static constexpr int SMEM_BYTES = 81920;

__global__ void __launch_bounds__(256, 2) lokr_fused(
    const float* __restrict__ x,
    const float* __restrict__ w1a, const float* __restrict__ w1b,
    const float* __restrict__ w2a, const float* __restrict__ w2b,
    float* __restrict__ out, int rows)
{
    extern __shared__ __align__(16) char smem[];
    float*  Xbuf   = reinterpret_cast<float*>(smem);
    float*  Cs     = reinterpret_cast<float*>(smem + 65536);
    float4* w1bp_s = reinterpret_cast<float4*>(smem + 69632);
    float4* w2b4_s = reinterpret_cast<float4*>(smem + 73728);
    float*  w1a_s  = reinterpret_cast<float*>(smem + 77824);
    float*  Ps     = Xbuf;          // alias, X dead after step 1
    float*  Qs     = Xbuf + 4096;   // alias (X rows 1-2 region, dead after step 1)

    const int tid = threadIdx.x;
    const int r   = tid >> 6;       // row-sub 0..3
    const int s   = tid & 63;       // lane within row slice

    // ---- one-time weight setup ----
    {
        int m = tid >> 2, jg = tid & 3;
        w1bp_s[tid] = make_float4(w1b[m * 16 + jg],
                                  w1b[m * 16 + jg + 4],
                                  w1b[m * 16 + jg + 8],
                                  w1b[m * 16 + jg + 12]);
        w2b4_s[tid] = reinterpret_cast<const float4*>(w2b)[tid];
        float4 wa = reinterpret_cast<const float4*>(w1a)[tid];
        reinterpret_cast<float4*>(w1a_s)[tid] =
            make_float4(SCALING * wa.x, SCALING * wa.y, SCALING * wa.z, SCALING * wa.w);
    }
    // w2a held in registers for the whole kernel (loop-invariant).
    float4 Wreg[16];
    {
        const int kq = tid & 15;
#pragma unroll
        for (int t = 0; t < 16; t++)
            Wreg[t] = *reinterpret_cast<const float4*>(w2a + t * 64 + kq * 4);
    }
    __syncthreads();

    const int nIter = (rows + 3) >> 2;

    for (int iter = blockIdx.x; iter < nIter; iter += gridDim.x) {
        const int  my_row = iter * 4 + r;
        const bool valid  = (my_row < rows);

        // ---- stage X row into smem (coalesced float4) ----
        if (valid) {
            const float4* src = reinterpret_cast<const float4*>(x) + (size_t)my_row * 1024;
            float4* dst = reinterpret_cast<float4*>(Xbuf + r * 4096);
#pragma unroll
            for (int i = 0; i < 16; i++)
                dst[s + 64 * i] = src[s + 64 * i];
        }
        __syncthreads();

        // ---- Step 1: P[j,n] = sum_m w1b[m,j] X[m,n] ----
        // thread: ng = s>>2 (n0 = 4*ng), jg = s&3 (j in {jg, jg+4, jg+8, jg+12})
        const int ng = s >> 2, jg = s & 3, n0 = ng * 4;
        float2 acc1[8];
#pragma unroll
        for (int i = 0; i < 8; i++) acc1[i] = make_float2(0.f, 0.f);
        {
            const float* Xr = Xbuf + r * 4096;
#pragma unroll 8
            for (int m = 0; m < 64; m++) {
                float4 X4 = *reinterpret_cast<const float4*>(Xr + m * 64 + n0);
                float4 W4 = w1bp_s[m * 4 + jg];
                float2 xa = make_float2(X4.x, X4.y), xb = make_float2(X4.z, X4.w);
                acc1[0] = ffma2(make_float2(W4.x, W4.x), xa, acc1[0]);
                acc1[1] = ffma2(make_float2(W4.x, W4.x), xb, acc1[1]);
                acc1[2] = ffma2(make_float2(W4.y, W4.y), xa, acc1[2]);
                acc1[3] = ffma2(make_float2(W4.y, W4.y), xb, acc1[3]);
                acc1[4] = ffma2(make_float2(W4.z, W4.z), xa, acc1[4]);
                acc1[5] = ffma2(make_float2(W4.z, W4.z), xb, acc1[5]);
                acc1[6] = ffma2(make_float2(W4.w, W4.w), xa, acc1[6]);
                acc1[7] = ffma2(make_float2(W4.w, W4.w), xb, acc1[7]);
            }
        }
        __syncthreads();   // all X reads done before P overwrites Xbuf
        {
            float* Pr = Ps + r * 1024;
#pragma unroll
            for (int u = 0; u < 4; u++)
                *reinterpret_cast<float4*>(Pr + (jg + 4 * u) * 64 + n0) =
                    make_float4(acc1[2 * u].x, acc1[2 * u].y,
                                acc1[2 * u + 1].x, acc1[2 * u + 1].y);
        }
        __syncthreads();

        // ---- Step 2: C[j,t] = sum_n P[j,n] w2b[n,t] ----
        // thread: j = s>>2, tg = s&3 (t = 4tg..4tg+3)
        {
            const int j = s >> 2, tg = s & 3;
            const float* Pr = Ps + r * 1024 + j * 64;
            float2 c01 = make_float2(0.f, 0.f), c23 = make_float2(0.f, 0.f);
#pragma unroll
            for (int nb = 0; nb < 16; nb++) {
                float4 P4  = *reinterpret_cast<const float4*>(Pr + nb * 4);
                float4 Wn0 = w2b4_s[(nb * 4 + 0) * 4 + tg];
                float4 Wn1 = w2b4_s[(nb * 4 + 1) * 4 + tg];
                float4 Wn2 = w2b4_s[(nb * 4 + 2) * 4 + tg];
                float4 Wn3 = w2b4_s[(nb * 4 + 3) * 4 + tg];
                c01 = ffma2(make_float2(P4.x, P4.x), make_float2(Wn0.x, Wn0.y), c01);
                c23 = ffma2(make_float2(P4.x, P4.x), make_float2(Wn0.z, Wn0.w), c23);
                c01 = ffma2(make_float2(P4.y, P4.y), make_float2(Wn1.x, Wn1.y), c01);
                c23 = ffma2(make_float2(P4.y, P4.y), make_float2(Wn1.z, Wn1.w), c23);
                c01 = ffma2(make_float2(P4.z, P4.z), make_float2(Wn2.x, Wn2.y), c01);
                c23 = ffma2(make_float2(P4.z, P4.z), make_float2(Wn2.z, Wn2.w), c23);
                c01 = ffma2(make_float2(P4.w, P4.w), make_float2(Wn3.x, Wn3.y), c01);
                c23 = ffma2(make_float2(P4.w, P4.w), make_float2(Wn3.z, Wn3.w), c23);
            }
            *reinterpret_cast<float4*>(Cs + r * 256 + j * 16 + tg * 4) =
                make_float4(c01.x, c01.y, c23.x, c23.y);
        }
        __syncthreads();

        // ---- Step 3: Q[l,t] = S * sum_j w1a[j,l] C[j,t] ----
        // thread: l = s
        {
            const int l = s;
            float2 q[8];
#pragma unroll
            for (int i = 0; i < 8; i++) q[i] = make_float2(0.f, 0.f);
            const float* Cr = Cs + r * 256;
#pragma unroll
            for (int j = 0; j < 16; j++) {
                float  wv = w1a_s[j * 64 + l];
                float2 wd = make_float2(wv, wv);
                const float4* C4 = reinterpret_cast<const float4*>(Cr + j * 16);
#pragma unroll
                for (int u = 0; u < 4; u++) {
                    float4 cv = C4[u];
                    q[2 * u]     = ffma2(wd, make_float2(cv.x, cv.y), q[2 * u]);
                    q[2 * u + 1] = ffma2(wd, make_float2(cv.z, cv.w), q[2 * u + 1]);
                }
            }
            float* Qr = Qs + r * 1280 + l * 20;
#pragma unroll
            for (int u = 0; u < 4; u++)
                *reinterpret_cast<float4*>(Qr + 4 * u) =
                    make_float4(q[2 * u].x, q[2 * u].y, q[2 * u + 1].x, q[2 * u + 1].y);
        }
        __syncthreads();

        // ---- Step 4: Y[l,k] = sum_t Q[l,t] w2a[t,k]; w2a in registers ----
        // thread: kq = s&15 (k0 = 4*kq), lg = s>>4 (0..3); l = lg + 4*i, i = 0..15
        // -> full coverage of all 64 l values (this was the round-2 bug: only i<4).
        {
            const int kq = s & 15, lg = s >> 4;
            const int k0 = kq * 4;
            float* orow = out + (size_t)my_row * 4096;
#pragma unroll
            for (int i = 0; i < 16; i++) {
                const int l = lg + 4 * i;
                const float4* Q4 = reinterpret_cast<const float4*>(Qs + r * 1280 + l * 20);
                float2 a01 = make_float2(0.f, 0.f), a23 = make_float2(0.f, 0.f);
#pragma unroll
                for (int u = 0; u < 4; u++) {
                    float4 qv = Q4[u];
                    float4 w;
                    w = Wreg[4 * u + 0];
                    a01 = ffma2(make_float2(qv.x, qv.x), make_float2(w.x, w.y), a01);
                    a23 = ffma2(make_float2(qv.x, qv.x), make_float2(w.z, w.w), a23);
                    w = Wreg[4 * u + 1];
                    a01 = ffma2(make_float2(qv.y, qv.y), make_float2(w.x, w.y), a01);
                    a23 = ffma2(make_float2(qv.y, qv.y), make_float2(w.z, w.w), a23);
                    w = Wreg[4 * u + 2];
                    a01 = ffma2(make_float2(qv.z, qv.z), make_float2(w.x, w.y), a01);
                    a23 = ffma2(make_float2(qv.z, qv.z), make_float2(w.z, w.w), a23);
                    w = Wreg[4 * u + 3];
                    a01 = ffma2(make_float2(qv.w, qv.w), make_float2(w.x, w.y), a01);
                    a23 = ffma2(make_float2(qv.w, qv.w), make_float2(w.z, w.w), a23);
                }
                if (valid)
                    *reinterpret_cast<float4*>(orow + l * 64 + k0) =
                        make_float4(a01.x, a01.y, a23.x, a23.y);
            }
        }
        __syncthreads();   // Q/P regions reused as X next iteration
    }
}

extern "C" void kernel_launch(void* const* d_in, const int* in_sizes, int n_in,
                              void* d_out, int out_size) {
    const float* x   = (const float*)d_in[0];
    const float* w1a = (const float*)d_in[1];
    const float* w1b = (const float*)d_in[2];
    const float* w2a = (const float*)d_in[3];
    const float* w2b = (const float*)d_in[4];
    float* out = (float*)d_out;

    int rows = in_sizes[0] / 4096;

    cudaFuncSetAttribute(lokr_fused, cudaFuncAttributeMaxDynamicSharedMemorySize,
                         SMEM_BYTES);
    lokr_fused<<<296, 256, SMEM_BYTES>>>(x, w1a, w1b, w2a, w2b, out, rows);
}